// round 5
// baseline (speedup 1.0000x reference)
#include <cuda_runtime.h>

#define T_ 2048
#define B_ 256
#define M_ 32
#define HALF_ 16
#define NBLK 1024
#define FULL 0xffffffffu

__device__ float g_nllh[B_];
__device__ int g_done;

__device__ __forceinline__ float ex2f_(float x) {
    float y; asm("ex2.approx.ftz.f32 %0, %1;" : "=f"(y) : "f"(x)); return y;
}
__device__ __forceinline__ float lg2f_(float x) {
    float y; asm("lg2.approx.ftz.f32 %0, %1;" : "=f"(y) : "f"(x)); return y;
}
__device__ __forceinline__ float rcpf_(float x) {
    float y; asm("rcp.approx.ftz.f32 %0, %1;" : "=f"(y) : "f"(x)); return y;
}

// produce e-rows [chunk0*4 .. chunk0*4+15] for one step slot (4x STS.128, XOR swizzle)
__device__ __forceinline__ void produce16(float4* dst, int chunk0, int l7,
                                          const float* tr2, float invw) {
#pragma unroll
    for (int k4 = 0; k4 < 4; ++k4) {
        float4 v;
        v.x = ex2f_(tr2[4 * k4 + 0] * invw);
        v.y = ex2f_(tr2[4 * k4 + 1] * invw);
        v.z = ex2f_(tr2[4 * k4 + 2] * invw);
        v.w = ex2f_(tr2[4 * k4 + 3] * invw);
        dst[(chunk0 + k4) ^ l7] = v;
    }
}

// s_j = sum_i p_i * E_ij ; E loaded via 8x LDS.128 (swizzled, conflict-free)
__device__ __forceinline__ float matvec32(const float4* sl, int l7, float p) {
    float4 Eq[8];
#pragma unroll
    for (int k4 = 0; k4 < 8; ++k4)
        Eq[k4] = sl[k4 ^ l7];
    const float* E = (const float*)Eq;
    float a0 = 0.f, a1 = 0.f, a2 = 0.f, a3 = 0.f;
#pragma unroll
    for (int k = 0; k < 32; k += 4) {
        a0 = fmaf(__shfl_sync(FULL, p, k + 0), E[k + 0], a0);
        a1 = fmaf(__shfl_sync(FULL, p, k + 1), E[k + 1], a1);
        a2 = fmaf(__shfl_sync(FULL, p, k + 2), E[k + 2], a2);
        a3 = fmaf(__shfl_sync(FULL, p, k + 3), E[k + 3], a3);
    }
    return (a0 + a1) + (a2 + a3);
}

// exponent of lane-0's p (warp-uniform); p0 is always positive & normal here
__device__ __forceinline__ int exp_of_p0(float p, unsigned mask = FULL) {
    const float p0 = __shfl_sync(mask, p, 0);
    return (int)((__float_as_uint(p0) >> 23) & 255u) - 127;
}

__global__ __launch_bounds__(128, 1)
void crf_kernel(const float* __restrict__ em,     // [T,B,M]
                const int*   __restrict__ tags,   // [T,B]
                const float* __restrict__ wt,     // [T,B]
                const int*   __restrict__ mk,     // [T,B]
                const float* __restrict__ trans,  // [M,M]
                const float* __restrict__ startt, // [M]
                const float* __restrict__ endt,   // [M]
                float* __restrict__ out)
{
    const int lane = threadIdx.x & 31;
    const int warp = threadIdx.x >> 5;
    const int pair = warp >> 1;
    const int half = warp & 1;
    const int b = blockIdx.x * 2 + pair;
    const int i0 = half * HALF_;
    const int l7 = lane & 7;
    const float L2E = 1.4426950408889634f;
    const float LN2 = 0.6931471805599453f;

    // [pair][phase][slot][lane][chunk]  = 32 KB
    __shared__ float4 ebuf[2][2][2][32][8];
    __shared__ float s_sc[2][2];
    __shared__ int   s_cnt[2][2];
    __shared__ int   s_last;

    // this warp's 16 transition rows, pre-scaled by log2(e)
    float tr2[HALF_];
#pragma unroll
    for (int k = 0; k < HALF_; ++k)
        tr2[k] = trans[(i0 + k) * M_ + lane] * L2E;

    // init: p = 2^(alpha0*log2e - F)
    float a0v = startt[lane] + em[(size_t)b * M_ + lane];
    float b2 = a0v * L2E;
    int F = __float2int_rn(__shfl_sync(FULL, b2, 0));
    float p = ex2f_(b2 - (float)F);
    // pending renorm shift = exponent of current p0 (contractive, first-order)
    int e_pend = exp_of_p0(p);
    float cf = (float)e_pend;

    // pre-loop: produce E for steps 1,2 into phase 0
    produce16(ebuf[pair][0][0][lane], half * 4, l7, tr2, rcpf_(wt[b]));
    produce16(ebuf[pair][0][1][lane], half * 4, l7, tr2, rcpf_(wt[B_ + b]));

    // prefetch (block 0 consumes steps 1,2; produces E for steps 3,4)
    float emA = em[((size_t)1 * B_ + b) * M_ + lane];
    float emB = em[((size_t)2 * B_ + b) * M_ + lane];
    int mkA = mk[1 * B_ + b];
    int mkB = mk[2 * B_ + b];
    float wP0 = wt[2 * B_ + b];
    float wP1 = wt[3 * B_ + b];

    int ph = 0;
#pragma unroll 1
    for (int u = 0; u < NBLK; ++u) {
        asm volatile("bar.sync %0, 64;" :: "r"(1 + pair) : "memory");
        const int t0 = 1 + 2 * u;

        // --- prefetch for next block (long-latency loads first) ---
        const int tn = t0 + 2;
        const int iA = (tn <= T_ - 1) ? tn : T_ - 1;
        const int iB = (tn + 1 <= T_ - 1) ? tn + 1 : T_ - 1;
        const float emA_n = em[((size_t)iA * B_ + b) * M_ + lane];
        const float emB_n = em[((size_t)iB * B_ + b) * M_ + lane];
        const int mkA_n = (tn     <= T_ - 1) ? mk[iA * B_ + b] : 0;
        const int mkB_n = (tn + 1 <= T_ - 1) ? mk[iB * B_ + b] : 0;
        const int iw0i = (tn + 1 <= T_ - 2) ? tn + 1 : T_ - 2;
        const int iw1i = (tn + 2 <= T_ - 2) ? tn + 2 : T_ - 2;
        const float wP0_n = wt[iw0i * B_ + b];
        const float wP1_n = wt[iw1i * B_ + b];

        const float iw0 = rcpf_(wP0);
        const float iw1 = rcpf_(wP1);

        // --- step A ---
        const float qA = ex2f_(fmaf(emA, L2E, -cf));    // absorbs pending renorm
        produce16(ebuf[pair][ph ^ 1][0][lane], half * 4, l7, tr2, iw0);
        const float sA = matvec32(ebuf[pair][ph][0][lane], l7, p);
        if (mkA) { p = sA * qA; F += e_pend; }
        e_pend = exp_of_p0(p);
        cf = (float)e_pend;

        // --- step B ---
        const float qB = ex2f_(fmaf(emB, L2E, -cf));
        produce16(ebuf[pair][ph ^ 1][1][lane], half * 4, l7, tr2, iw1);
        const float sB = matvec32(ebuf[pair][ph][1][lane], l7, p);
        if (mkB) { p = sB * qB; F += e_pend; }
        e_pend = exp_of_p0(p);
        cf = (float)e_pend;

        emA = emA_n; emB = emB_n; mkA = mkA_n; mkB = mkB_n;
        wP0 = wP0_n; wP1 = wP1_n;
        ph ^= 1;
    }

    // alpha = (log2(p) + F) * ln2 ; logZ = logsumexp(alpha + end)
    float logZ;
    {
        const float alphaf = (lg2f_(p) + (float)F) * LN2;
        float v = alphaf + endt[lane];
        float mz = v;
#pragma unroll
        for (int off = 16; off; off >>= 1)
            mz = fmaxf(mz, __shfl_xor_sync(FULL, mz, off));
        float ez = ex2f_((v - mz) * L2E);
#pragma unroll
        for (int off = 16; off; off >>= 1)
            ez += __shfl_xor_sync(FULL, ez, off);
        logZ = fmaf(lg2f_(ez), LN2, mz);
    }

    // ---- gold-path score: each warp covers half the T range ----
    float sc = 0.f; int cnt = 0;
    const int tbeg = half * (T_ / 2);
#pragma unroll 2
    for (int base = tbeg; base < tbeg + T_ / 2; base += 32) {
        const int t = base + lane;
        const int m_t = mk[t * B_ + b];
        cnt += m_t;
        if (m_t) {
            const int tg = tags[t * B_ + b];
            sc += em[((size_t)t * B_ + b) * M_ + tg];
            if (t > 0) {
                const int mp = mk[(t - 1) * B_ + b];
                const int tgp = mp ? tags[(t - 1) * B_ + b] : 1;
                sc += trans[tgp * M_ + tg] * rcpf_(wt[(t - 1) * B_ + b]);
            }
        }
    }
#pragma unroll
    for (int off = 16; off; off >>= 1) {
        sc  += __shfl_xor_sync(FULL, sc, off);
        cnt += __shfl_xor_sync(FULL, cnt, off);
    }
    if (lane == 0) { s_sc[pair][half] = sc; s_cnt[pair][half] = cnt; }
    __syncthreads();
    if (half == 0 && lane == 0) {
        float st = s_sc[pair][0] + s_sc[pair][1];
        const int cn = s_cnt[pair][0] + s_cnt[pair][1];
        st += startt[tags[b]] + endt[tags[(size_t)(cn - 1) * B_ + b]];
        g_nllh[b] = logZ - st;
    }

    // ---- last-block deterministic final reduction ----
    __threadfence();
    __syncthreads();
    if (threadIdx.x == 0)
        s_last = (atomicAdd(&g_done, 1) == (int)gridDim.x - 1) ? 1 : 0;
    __syncthreads();
    if (s_last && warp == 0) {
        float v = 0.f;
#pragma unroll
        for (int k = 0; k < B_ / 32; ++k) {
            float x;
            asm volatile("ld.global.cg.f32 %0, [%1];" : "=f"(x) : "l"(g_nllh + k * 32 + lane));
            v += x;
        }
#pragma unroll
        for (int off = 16; off; off >>= 1)
            v += __shfl_xor_sync(FULL, v, off);
        if (lane == 0) { out[0] = v; g_done = 0; }
    }
}

extern "C" void kernel_launch(void* const* d_in, const int* in_sizes, int n_in,
                              void* d_out, int out_size)
{
    const float* em     = (const float*)d_in[0];
    const int*   tags   = (const int*)  d_in[1];
    const float* wt     = (const float*)d_in[2];
    const int*   mask   = (const int*)  d_in[3];
    const float* trans  = (const float*)d_in[4];
    const float* startt = (const float*)d_in[5];
    const float* endt   = (const float*)d_in[6];

    crf_kernel<<<B_ / 2, 128>>>(em, tags, wt, mask, trans, startt, endt, (float*)d_out);
}

// round 7
// speedup vs baseline: 2.3118x; 2.3118x over previous
#include <cuda_runtime.h>
#include <cstdint>

#define T_ 2048
#define B_ 256
#define M_ 32
#define HALF_ 16
#define FULL 0xffffffffu

__device__ float g_nllh[B_];
__device__ int g_done;

__device__ __forceinline__ float ex2f_(float x) {
    float y; asm("ex2.approx.ftz.f32 %0, %1;" : "=f"(y) : "f"(x)); return y;
}
__device__ __forceinline__ float lg2f_(float x) {
    float y; asm("lg2.approx.ftz.f32 %0, %1;" : "=f"(y) : "f"(x)); return y;
}
__device__ __forceinline__ float rcpf_(float x) {
    float y; asm("rcp.approx.ftz.f32 %0, %1;" : "=f"(y) : "f"(x)); return y;
}

// TT: step index (runtime ok). SLOT/SLOTN/PAR: compile-time literals.
// EC: E array consumed this step; EP: E array produced for step TT+1.
#define STEP(TT, SLOT, SLOTN, PAR, EC, EP) do {                              \
    /* matvec half: sh_j = sum_k p[i0+k] * EC[k] */                          \
    float c0 = 0.f, c1 = 0.f, c2 = 0.f, c3 = 0.f;                            \
    _Pragma("unroll")                                                        \
    for (int k = 0; k < HALF_; k += 4) {                                     \
        c0 = fmaf(__shfl_sync(FULL, p, i0 + k + 0), EC[k + 0], c0);          \
        c1 = fmaf(__shfl_sync(FULL, p, i0 + k + 1), EC[k + 1], c1);          \
        c2 = fmaf(__shfl_sync(FULL, p, i0 + k + 2), EC[k + 2], c2);          \
        c3 = fmaf(__shfl_sync(FULL, p, i0 + k + 3), EC[k + 3], c3);          \
    }                                                                        \
    const float sh = (c0 + c1) + (c2 + c3);                                  \
    /* produce E for step TT+1 (independent of sh) */                        \
    {                                                                        \
        const float iw = rcpf_(wb[SLOT]);                                    \
        const float dd = emb[SLOTN] * L2E;                                   \
        _Pragma("unroll")                                                    \
        for (int k = 0; k < HALF_; ++k)                                      \
            EP[k] = ex2f_(fmaf(tr2[k], iw, dd));                             \
    }                                                                        \
    /* exchange half-sums */                                                 \
    xch[PAR][pair][half][lane] = sh;                                         \
    asm volatile("bar.sync %0, 64;" :: "r"(1 + pair) : "memory");            \
    const float oth = xch[PAR][pair][half ^ 1][lane];                        \
    const float sf = half ? (oth + sh) : (sh + oth);                         \
    if (mkb[SLOT]) { p = sf * sc_prev; F += x_prev; }                        \
    /* renorm factor for next step (off critical path) */                    \
    {                                                                        \
        const float p0 = __shfl_sync(FULL, p, 0);                            \
        x_prev = (int)((__float_as_uint(p0) >> 23) & 255u) - 127;            \
        sc_prev = __uint_as_float((unsigned int)(127 - x_prev) << 23);       \
    }                                                                        \
    /* reload this slot for step TT+8 */                                     \
    {                                                                        \
        const int tn = (TT) + 8;                                             \
        const int tcl = (tn < T_) ? tn : (T_ - 1);                           \
        emb[SLOT] = em[((size_t)tcl * B_ + b) * M_ + lane];                  \
        mkb[SLOT] = (tn < T_) ? mk[tcl * B_ + b] : 0;                        \
        wb[SLOT]  = wt[tcl * B_ + b];                                        \
    }                                                                        \
} while (0)

__global__ __launch_bounds__(128, 1)
void crf_kernel(const float* __restrict__ em,     // [T,B,M]
                const int*   __restrict__ tags,   // [T,B]
                const float* __restrict__ wt,     // [T,B]
                const int*   __restrict__ mk,     // [T,B]
                const float* __restrict__ trans,  // [M,M]
                const float* __restrict__ startt, // [M]
                const float* __restrict__ endt,   // [M]
                float* __restrict__ out)
{
    const int lane = threadIdx.x & 31;
    const int warp = threadIdx.x >> 5;
    const int pair = warp >> 1;
    const int half = warp & 1;
    const int b = blockIdx.x * 2 + pair;
    const int i0 = half * HALF_;
    const float L2E = 1.4426950408889634f;
    const float LN2 = 0.6931471805599453f;

    __shared__ float xch[2][2][2][M_];  // [parity][pair][half][lane]
    __shared__ float s_sc[2][2];
    __shared__ int   s_cnt[2][2];
    __shared__ int   s_last;

    // this warp's 16 transition rows (row i0+k, col lane), pre-scaled by log2(e)
    float tr2[HALF_];
#pragma unroll
    for (int k = 0; k < HALF_; ++k)
        tr2[k] = trans[(i0 + k) * M_ + lane] * L2E;

    // init: p = 2^(alpha0*log2e - F)
    const float a0v = startt[lane] + em[(size_t)b * M_ + lane];
    const float b2 = a0v * L2E;
    int F = __float2int_rn(__shfl_sync(FULL, b2, 0));
    float p = ex2f_(b2 - (float)F);
    int x_prev;
    float sc_prev;
    {
        const float p0 = __shfl_sync(FULL, p, 0);
        x_prev = (int)((__float_as_uint(p0) >> 23) & 255u) - 127;
        sc_prev = __uint_as_float((unsigned int)(127 - x_prev) << 23);
    }

    // 8-slot ring: slot t&7 holds em[t], mk[t], wt[t] (wt[t] feeds E of step t+1)
    float emb[8], wb[8]; int mkb[8];
#pragma unroll
    for (int j = 0; j < 8; ++j) {
        const int t = 1 + j;          // steps 1..8 -> slots 1..7,0
        const int sl = t & 7;
        emb[sl] = em[((size_t)t * B_ + b) * M_ + lane];
        mkb[sl] = mk[t * B_ + b];
        wb[sl]  = wt[t * B_ + b];
    }

    // E for step 1: uses wt[0] and em[1]
    float eA[HALF_], eB[HALF_];
    {
        const float iw = rcpf_(wt[b]);
        const float dd = emb[1] * L2E;
#pragma unroll
        for (int k = 0; k < HALF_; ++k)
            eA[k] = ex2f_(fmaf(tr2[k], iw, dd));
    }

    // 256 iterations x 8 steps = steps 1..2048 (step 2048 is fake, mk=0)
#pragma unroll 1
    for (int u = 0; u < 256; ++u) {
        const int t0 = 1 + 8 * u;
        STEP(t0 + 0, 1, 2, 1, eA, eB);
        STEP(t0 + 1, 2, 3, 0, eB, eA);
        STEP(t0 + 2, 3, 4, 1, eA, eB);
        STEP(t0 + 3, 4, 5, 0, eB, eA);
        STEP(t0 + 4, 5, 6, 1, eA, eB);
        STEP(t0 + 5, 6, 7, 0, eB, eA);
        STEP(t0 + 6, 7, 0, 1, eA, eB);
        STEP(t0 + 7, 0, 1, 0, eB, eA);
    }

    // alpha = (log2(p) + F) * ln2 ; logZ = logsumexp(alpha + end)
    float logZ;
    {
        const float alphaf = (lg2f_(p) + (float)F) * LN2;
        float v = alphaf + endt[lane];
        float mz = v;
#pragma unroll
        for (int off = 16; off; off >>= 1)
            mz = fmaxf(mz, __shfl_xor_sync(FULL, mz, off));
        float ez = ex2f_((v - mz) * L2E);
#pragma unroll
        for (int off = 16; off; off >>= 1)
            ez += __shfl_xor_sync(FULL, ez, off);
        logZ = fmaf(lg2f_(ez), LN2, mz);
    }

    // ---- gold-path score: each warp covers half the T range ----
    float sc = 0.f; int cnt = 0;
    const int tbeg = half * (T_ / 2);
#pragma unroll 2
    for (int base = tbeg; base < tbeg + T_ / 2; base += 32) {
        const int t = base + lane;
        const int m_t = mk[t * B_ + b];
        cnt += m_t;
        if (m_t) {
            const int tg = tags[t * B_ + b];
            sc += em[((size_t)t * B_ + b) * M_ + tg];
            if (t > 0) {
                const int mp = mk[(t - 1) * B_ + b];
                const int tgp = mp ? tags[(t - 1) * B_ + b] : 1;
                sc += trans[tgp * M_ + tg] * rcpf_(wt[(t - 1) * B_ + b]);
            }
        }
    }
#pragma unroll
    for (int off = 16; off; off >>= 1) {
        sc  += __shfl_xor_sync(FULL, sc, off);
        cnt += __shfl_xor_sync(FULL, cnt, off);
    }
    if (lane == 0) { s_sc[pair][half] = sc; s_cnt[pair][half] = cnt; }
    __syncthreads();
    if (half == 0 && lane == 0) {
        float st = s_sc[pair][0] + s_sc[pair][1];
        const int cn = s_cnt[pair][0] + s_cnt[pair][1];
        st += startt[tags[b]] + endt[tags[(size_t)(cn - 1) * B_ + b]];
        g_nllh[b] = logZ - st;
    }

    // ---- last-block deterministic final reduction ----
    __threadfence();
    __syncthreads();
    if (threadIdx.x == 0)
        s_last = (atomicAdd(&g_done, 1) == (int)gridDim.x - 1) ? 1 : 0;
    __syncthreads();
    if (s_last && warp == 0) {
        float v = 0.f;
#pragma unroll
        for (int k = 0; k < B_ / 32; ++k) {
            float x;
            asm volatile("ld.global.cg.f32 %0, [%1];" : "=f"(x) : "l"(g_nllh + k * 32 + lane));
            v += x;
        }
#pragma unroll
        for (int off = 16; off; off >>= 1)
            v += __shfl_xor_sync(FULL, v, off);
        if (lane == 0) { out[0] = v; g_done = 0; }
    }
}

extern "C" void kernel_launch(void* const* d_in, const int* in_sizes, int n_in,
                              void* d_out, int out_size)
{
    const float* em     = (const float*)d_in[0];
    const int*   tags   = (const int*)  d_in[1];
    const float* wt     = (const float*)d_in[2];
    const int*   mask   = (const int*)  d_in[3];
    const float* trans  = (const float*)d_in[4];
    const float* startt = (const float*)d_in[5];
    const float* endt   = (const float*)d_in[6];

    crf_kernel<<<B_ / 2, 128>>>(em, tags, wt, mask, trans, startt, endt, (float*)d_out);
}